// round 15
// baseline (speedup 1.0000x reference)
#include <cuda_runtime.h>
#include <cuda_bf16.h>
#include <math.h>
#include <stdint.h>

#define H   16
#define HD  64
#define NQ  2048
#define NKV 4096
#define CD  1024
#define KDIM 1024

typedef unsigned long long u64;
typedef unsigned int u32;

// ---------------- cp.async helpers ----------------
__device__ __forceinline__ void cp16(u32 smem_addr, const void* gptr) {
    asm volatile("cp.async.cg.shared.global [%0], [%1], 16;"
                 :: "r"(smem_addr), "l"(gptr));
}
__device__ __forceinline__ void cp_commit() {
    asm volatile("cp.async.commit_group;");
}
template<int N> __device__ __forceinline__ void cp_wait() {
    asm volatile("cp.async.wait_group %0;" :: "n"(N));
}
__device__ __forceinline__ u32 smem_u32(const void* p) {
    return (u32)__cvta_generic_to_shared(p);
}

// ---------------- scratch (device globals: allocation-free) ----------------
__device__ __align__(16) float g_qkv[NQ * 3 * CD];
__device__ __align__(16) float g_kv [NQ * 2 * CD];
__device__ __align__(16) float g_o  [NQ * CD];

// pre-split bf16 attention operands
__device__ __align__(16) __nv_bfloat16 g_qh[H*NQ*HD],  g_ql[H*NQ*HD];   // [h][n][d], 0.125 baked in
__device__ __align__(16) __nv_bfloat16 g_kh[H*NKV*HD], g_kl[H*NKV*HD];  // [h][key][d]
__device__ __align__(16) __nv_bfloat16 g_vth[H*HD*NKV], g_vtl[H*HD*NKV];// [h][d][key]

// bf16 split operand buffers for projection GEMMs
__device__ __align__(16) __nv_bfloat16 g_xh[NQ*CD],  g_xl[NQ*CD];    // x, reused for o
__device__ __align__(16) __nv_bfloat16 g_yh[NQ*CD],  g_yl[NQ*CD];
__device__ __align__(16) __nv_bfloat16 g_wqh[3*CD*CD], g_wql[3*CD*CD];
__device__ __align__(16) __nv_bfloat16 g_wkh[2*CD*CD], g_wkl[2*CD*CD];
__device__ __align__(16) __nv_bfloat16 g_wph[CD*CD],   g_wpl[CD*CD];

// ---------------- helpers --------------------------------------------------
__device__ __forceinline__ void split1(float v, __nv_bfloat16& h, __nv_bfloat16& l) {
    h = __float2bfloat16_rn(v);
    l = __float2bfloat16_rn(v - __bfloat162float(h));
}
__device__ __forceinline__ u32 packbf2(float lo, float hi) {
    u32 r;
    asm("cvt.rn.bf16x2.f32 %0, %1, %2;" : "=r"(r) : "f"(hi), "f"(lo));
    return r;
}
__device__ __forceinline__ void mma_bf16(float* c, const u32* a, const u32* b) {
    asm volatile(
        "mma.sync.aligned.m16n8k16.row.col.f32.bf16.bf16.f32 "
        "{%0,%1,%2,%3}, {%4,%5,%6,%7}, {%8,%9}, {%0,%1,%2,%3};"
        : "+f"(c[0]), "+f"(c[1]), "+f"(c[2]), "+f"(c[3])
        : "r"(a[0]), "r"(a[1]), "r"(a[2]), "r"(a[3]), "r"(b[0]), "r"(b[1]));
}

// ---------------- split: fp32 -> bf16 hi + bf16 lo -------------------------
__global__ __launch_bounds__(256) void split_kernel(
    const float* __restrict__ src, __nv_bfloat16* __restrict__ hi,
    __nv_bfloat16* __restrict__ lo, int n4)
{
    int i = blockIdx.x * 256 + threadIdx.x;
    if (i >= n4) return;
    float4 v = ((const float4*)src)[i];
    __nv_bfloat16 h0, h1, h2, h3, l0, l1, l2, l3;
    split1(v.x, h0, l0); split1(v.y, h1, l1);
    split1(v.z, h2, l2); split1(v.w, h3, l3);
    __nv_bfloat162* hp = (__nv_bfloat162*)(hi + (size_t)i*4);
    __nv_bfloat162* lp = (__nv_bfloat162*)(lo + (size_t)i*4);
    hp[0] = __nv_bfloat162(h0, h1); hp[1] = __nv_bfloat162(h2, h3);
    lp[0] = __nv_bfloat162(l0, l1); lp[1] = __nv_bfloat162(l2, l3);
}

// ============ bf16-split tensor-core GEMM, cp.async double-buffered ========
// 128x128 tile, BK=32, 256 threads (8 warps, 4M x 2N), mma.sync m16n8k16.
#define SA 40                     // smem row stride (bf16): 80B, 16B-aligned
#define G_ARR  (128*SA*2)         // bytes per array per stage = 10240
#define G_STG  (4*G_ARR)          // stage size = 40960
#define G_SMEM (2*G_STG)          // 81920

__global__ __launch_bounds__(256, 2) void gemm_bf16(
    const __nv_bfloat16* __restrict__ Ah, const __nv_bfloat16* __restrict__ Al,
    const __nv_bfloat16* __restrict__ Bh, const __nv_bfloat16* __restrict__ Bl,
    float* __restrict__ Cp, const float* __restrict__ bias, int N)
{
    extern __shared__ __align__(16) char dsm[];
    const int tid = threadIdx.x;
    const int wid = tid >> 5, lane = tid & 31;
    const int wm = wid & 3, wn = wid >> 2;
    const int grp = lane >> 2, tq = lane & 3;
    const int bm = blockIdx.y * 128, bn = blockIdx.x * 128;

    const int lrow = tid >> 2, lkc = tid & 3;        // load mapping (2 rows/thread)
    const u32 sbase = smem_u32(dsm);

    // issue async loads of one 128x32 k-tile (4 arrays) into stage st
    auto load_tile = [&](int kt, int st) {
        #pragma unroll
        for (int i = 0; i < 2; i++) {
            int row = lrow + i*64;
            size_t goA = (size_t)(bm + row) * KDIM + kt + lkc*8;
            size_t goB = (size_t)(bn + row) * KDIM + kt + lkc*8;
            u32 so = sbase + st*G_STG + row*(SA*2) + lkc*16;
            cp16(so,           Ah + goA);
            cp16(so + G_ARR,   Al + goA);
            cp16(so + 2*G_ARR, Bh + goB);
            cp16(so + 3*G_ARR, Bl + goB);
        }
    };

    float acc[2][8][4] = {};

    load_tile(0, 0);
    cp_commit();

    for (int t = 0; t < KDIM/32; t++) {
        int st = t & 1;
        if (t < KDIM/32 - 1) {
            load_tile((t+1)*32, st ^ 1);
            cp_commit();
            cp_wait<1>();
        } else {
            cp_wait<0>();
        }
        __syncthreads();

        const __nv_bfloat16* sAh = (const __nv_bfloat16*)(dsm + st*G_STG);
        const __nv_bfloat16* sAl = (const __nv_bfloat16*)(dsm + st*G_STG + G_ARR);
        const __nv_bfloat16* sBh = (const __nv_bfloat16*)(dsm + st*G_STG + 2*G_ARR);
        const __nv_bfloat16* sBl = (const __nv_bfloat16*)(dsm + st*G_STG + 3*G_ARR);

        #pragma unroll
        for (int ks = 0; ks < 32; ks += 16) {
            u32 ah[8], al[8];
            #pragma unroll
            for (int mt = 0; mt < 2; mt++) {
                int r0 = (wm*32 + mt*16 + grp) * SA + ks + 2*tq;
                int r1 = r0 + 8*SA;
                ah[mt*4+0] = *(const u32*)&sAh[r0];
                ah[mt*4+1] = *(const u32*)&sAh[r1];
                ah[mt*4+2] = *(const u32*)&sAh[r0 + 8];
                ah[mt*4+3] = *(const u32*)&sAh[r1 + 8];
                al[mt*4+0] = *(const u32*)&sAl[r0];
                al[mt*4+1] = *(const u32*)&sAl[r1];
                al[mt*4+2] = *(const u32*)&sAl[r0 + 8];
                al[mt*4+3] = *(const u32*)&sAl[r1 + 8];
            }
            #pragma unroll
            for (int nt = 0; nt < 8; nt++) {
                int b0 = (wn*64 + nt*8 + grp) * SA + ks + 2*tq;
                u32 bh[2], bl[2];
                bh[0] = *(const u32*)&sBh[b0];
                bh[1] = *(const u32*)&sBh[b0 + 8];
                bl[0] = *(const u32*)&sBl[b0];
                bl[1] = *(const u32*)&sBl[b0 + 8];
                mma_bf16(acc[0][nt], ah,   bh);
                mma_bf16(acc[1][nt], ah+4, bh);
                mma_bf16(acc[0][nt], ah,   bl);
                mma_bf16(acc[1][nt], ah+4, bl);
                mma_bf16(acc[0][nt], al,   bh);
                mma_bf16(acc[1][nt], al+4, bh);
            }
        }
        __syncthreads();
    }

    #pragma unroll
    for (int mt = 0; mt < 2; mt++) {
        int row0 = bm + wm*32 + mt*16 + grp;
        #pragma unroll
        for (int nt = 0; nt < 8; nt++) {
            int col = bn + wn*64 + nt*8 + 2*tq;
            float b0 = 0.f, b1 = 0.f;
            if (bias) { b0 = bias[col]; b1 = bias[col+1]; }
            float2 v0 = make_float2(acc[mt][nt][0] + b0, acc[mt][nt][1] + b1);
            float2 v1 = make_float2(acc[mt][nt][2] + b0, acc[mt][nt][3] + b1);
            *(float2*)(Cp + (size_t)row0       * N + col) = v0;
            *(float2*)(Cp + (size_t)(row0 + 8) * N + col) = v1;
        }
    }
}

// ------------- x path: RMSNorm + RoPE, emit split bf16 q/k/v ---------------
__global__ __launch_bounds__(256) void post_x(
    const float* __restrict__ pos,
    const float* __restrict__ qw, const float* __restrict__ kw)
{
    int wid  = blockIdx.x * 8 + (threadIdx.x >> 5);
    int lane = threadIdx.x & 31;
    int n = wid >> 4;
    int h = wid & 15;
    const float* base = g_qkv + (size_t)n * 3072 + h * 64 + lane * 2;
    float2 q2 = *(const float2*)(base);
    float2 k2 = *(const float2*)(base + 1024);
    float2 v2 = *(const float2*)(base + 2048);
    float sq = q2.x*q2.x + q2.y*q2.y;
    float sk = k2.x*k2.x + k2.y*k2.y;
    #pragma unroll
    for (int off = 16; off > 0; off >>= 1) {
        sq += __shfl_xor_sync(0xffffffffu, sq, off);
        sk += __shfl_xor_sync(0xffffffffu, sk, off);
    }
    float rq = rsqrtf(sq * (1.f/64.f) + 1e-6f);
    float rk = rsqrtf(sk * (1.f/64.f) + 1e-6f);
    float2 wq = *(const float2*)(qw + lane*2);
    float2 wk = *(const float2*)(kw + lane*2);
    float qe = q2.x * rq * wq.x, qo = q2.y * rq * wq.y;
    float ke = k2.x * rk * wk.x, ko = k2.y * rk * wk.y;
    float2 cs = *(const float2*)(pos + (size_t)n*64 + lane*2);
    float qx = (qe*cs.x - qo*cs.y) * 0.125f;
    float qy = (qe*cs.y + qo*cs.x) * 0.125f;
    float kx = ke*cs.x - ko*cs.y;
    float ky = ke*cs.y + ko*cs.x;

    __nv_bfloat16 hh, ll, hh2, ll2;
    size_t qi = ((size_t)h*NQ + n)*64 + lane*2;
    split1(qx, hh, ll); split1(qy, hh2, ll2);
    *(__nv_bfloat162*)&g_qh[qi] = __nv_bfloat162(hh, hh2);
    *(__nv_bfloat162*)&g_ql[qi] = __nv_bfloat162(ll, ll2);
    size_t ki = ((size_t)h*NKV + n)*64 + lane*2;
    split1(kx, hh, ll); split1(ky, hh2, ll2);
    *(__nv_bfloat162*)&g_kh[ki] = __nv_bfloat162(hh, hh2);
    *(__nv_bfloat162*)&g_kl[ki] = __nv_bfloat162(ll, ll2);
    size_t v0 = ((size_t)h*64 + lane*2) * NKV + n;
    split1(v2.x, hh, ll);
    g_vth[v0] = hh; g_vtl[v0] = ll;
    split1(v2.y, hh, ll);
    g_vth[v0 + NKV] = hh; g_vtl[v0 + NKV] = ll;
}

// ------------- y path: RMSNorm(ky), split k/v at key 2048+ -----------------
__global__ __launch_bounds__(256) void post_y(const float* __restrict__ kw)
{
    int wid  = blockIdx.x * 8 + (threadIdx.x >> 5);
    int lane = threadIdx.x & 31;
    int m = wid >> 4;
    int h = wid & 15;
    const float* base = g_kv + (size_t)m * 2048 + h * 64 + lane * 2;
    float2 k2 = *(const float2*)(base);
    float2 v2 = *(const float2*)(base + 1024);
    float sk = k2.x*k2.x + k2.y*k2.y;
    #pragma unroll
    for (int off = 16; off > 0; off >>= 1)
        sk += __shfl_xor_sync(0xffffffffu, sk, off);
    float rk = rsqrtf(sk * (1.f/64.f) + 1e-6f);
    float2 wk = *(const float2*)(kw + lane*2);
    float kx = k2.x * rk * wk.x, ky = k2.y * rk * wk.y;

    __nv_bfloat16 hh, ll, hh2, ll2;
    size_t ki = ((size_t)h*NKV + 2048 + m)*64 + lane*2;
    split1(kx, hh, ll); split1(ky, hh2, ll2);
    *(__nv_bfloat162*)&g_kh[ki] = __nv_bfloat162(hh, hh2);
    *(__nv_bfloat162*)&g_kl[ki] = __nv_bfloat162(ll, ll2);
    size_t v0 = ((size_t)h*64 + lane*2) * NKV + 2048 + m;
    split1(v2.x, hh, ll);
    g_vth[v0] = hh; g_vtl[v0] = ll;
    split1(v2.y, hh, ll);
    g_vth[v0 + NKV] = hh; g_vtl[v0 + NKV] = ll;
}

// ---------------- flash attention via mma.sync, cp.async pipelined ---------
#define FS 72                      // smem tile row stride (bf16)
#define F_ARR  (64*FS*2)           // 9216 B per array per stage
#define F_STG  (4*F_ARR)           // 36864
#define F_SMEM (2*F_STG)           // 73728

__global__ __launch_bounds__(128) void flash_mma()
{
    extern __shared__ __align__(16) char dsm[];
    const int h  = blockIdx.y;
    const int qt = blockIdx.x;
    const int tid = threadIdx.x;
    const int wid = tid >> 5, lane = tid & 31;
    const int gid = lane >> 2, tq = lane & 3;
    const int qrow = qt*64 + wid*16 + gid;
    const u32 sbase = smem_u32(dsm);

    const int lrow = tid >> 1, lhf = tid & 1;   // tile-load mapping

    auto load_tile = [&](int kt, int st) {
        const __nv_bfloat16* gkh = g_kh + ((size_t)h*NKV + kt + lrow)*64 + lhf*32;
        const __nv_bfloat16* gkl = g_kl + ((size_t)h*NKV + kt + lrow)*64 + lhf*32;
        const __nv_bfloat16* gvh = g_vth + ((size_t)h*64 + lrow)*NKV + kt + lhf*32;
        const __nv_bfloat16* gvl = g_vtl + ((size_t)h*64 + lrow)*NKV + kt + lhf*32;
        u32 so = sbase + st*F_STG + lrow*(FS*2) + lhf*64;
        #pragma unroll
        for (int i = 0; i < 4; i++) {
            cp16(so + i*16,            gkh + i*8);
            cp16(so + i*16 + F_ARR,    gkl + i*8);
            cp16(so + i*16 + 2*F_ARR,  gvh + i*8);
            cp16(so + i*16 + 3*F_ARR,  gvl + i*8);
        }
    };

    // Q fragments (hi/lo), resident for whole kernel
    u32 aqh[16], aql[16];
    #pragma unroll
    for (int ks = 0; ks < 4; ks++) {
        size_t b = ((size_t)h*NQ + qrow)*64 + ks*16 + 2*tq;
        aqh[ks*4+0] = *(const u32*)&g_qh[b];
        aqh[ks*4+1] = *(const u32*)&g_qh[b + 8*64];
        aqh[ks*4+2] = *(const u32*)&g_qh[b + 8];
        aqh[ks*4+3] = *(const u32*)&g_qh[b + 8*64 + 8];
        aql[ks*4+0] = *(const u32*)&g_ql[b];
        aql[ks*4+1] = *(const u32*)&g_ql[b + 8*64];
        aql[ks*4+2] = *(const u32*)&g_ql[b + 8];
        aql[ks*4+3] = *(const u32*)&g_ql[b + 8*64 + 8];
    }

    float oa[8][4] = {};
    float m0 = -INFINITY, m1 = -INFINITY, l0 = 0.f, l1 = 0.f;

    load_tile(0, 0);
    cp_commit();

    for (int t = 0; t < NKV/64; t++) {
        int st = t & 1;
        if (t < NKV/64 - 1) {
            load_tile((t+1)*64, st ^ 1);
            cp_commit();
            cp_wait<1>();
        } else {
            cp_wait<0>();
        }
        __syncthreads();

        const __nv_bfloat16* sKh = (const __nv_bfloat16*)(dsm + st*F_STG);
        const __nv_bfloat16* sKl = (const __nv_bfloat16*)(dsm + st*F_STG + F_ARR);
        const __nv_bfloat16* sVh = (const __nv_bfloat16*)(dsm + st*F_STG + 2*F_ARR);
        const __nv_bfloat16* sVl = (const __nv_bfloat16*)(dsm + st*F_STG + 3*F_ARR);

        // ---- S = Q K^T ----
        float s[8][4] = {};
        #pragma unroll
        for (int ks = 0; ks < 4; ks++) {
            #pragma unroll
            for (int j = 0; j < 8; j++) {
                int ko = (8*j + gid)*FS + ks*16 + 2*tq;
                u32 bh[2], bl[2];
                bh[0] = *(const u32*)&sKh[ko];
                bh[1] = *(const u32*)&sKh[ko + 8];
                bl[0] = *(const u32*)&sKl[ko];
                bl[1] = *(const u32*)&sKl[ko + 8];
                mma_bf16(s[j], &aqh[ks*4], bh);
                mma_bf16(s[j], &aqh[ks*4], bl);
                mma_bf16(s[j], &aql[ks*4], bh);
            }
        }

        // ---- online softmax ----
        float mx0 = -INFINITY, mx1 = -INFINITY;
        #pragma unroll
        for (int j = 0; j < 8; j++) {
            mx0 = fmaxf(mx0, fmaxf(s[j][0], s[j][1]));
            mx1 = fmaxf(mx1, fmaxf(s[j][2], s[j][3]));
        }
        mx0 = fmaxf(mx0, __shfl_xor_sync(0xffffffffu, mx0, 1));
        mx0 = fmaxf(mx0, __shfl_xor_sync(0xffffffffu, mx0, 2));
        mx1 = fmaxf(mx1, __shfl_xor_sync(0xffffffffu, mx1, 1));
        mx1 = fmaxf(mx1, __shfl_xor_sync(0xffffffffu, mx1, 2));
        float mn0 = fmaxf(m0, mx0), mn1 = fmaxf(m1, mx1);
        float al0 = __expf(m0 - mn0), al1 = __expf(m1 - mn1);
        m0 = mn0; m1 = mn1;
        float ps0 = 0.f, ps1 = 0.f;
        #pragma unroll
        for (int j = 0; j < 8; j++) {
            s[j][0] = __expf(s[j][0] - mn0);
            s[j][1] = __expf(s[j][1] - mn0);
            s[j][2] = __expf(s[j][2] - mn1);
            s[j][3] = __expf(s[j][3] - mn1);
            ps0 += s[j][0] + s[j][1];
            ps1 += s[j][2] + s[j][3];
        }
        ps0 += __shfl_xor_sync(0xffffffffu, ps0, 1);
        ps0 += __shfl_xor_sync(0xffffffffu, ps0, 2);
        ps1 += __shfl_xor_sync(0xffffffffu, ps1, 1);
        ps1 += __shfl_xor_sync(0xffffffffu, ps1, 2);
        l0 = l0*al0 + ps0;
        l1 = l1*al1 + ps1;
        #pragma unroll
        for (int j = 0; j < 8; j++) {
            oa[j][0] *= al0; oa[j][1] *= al0;
            oa[j][2] *= al1; oa[j][3] *= al1;
        }

        // ---- O += P V ----
        #pragma unroll
        for (int ks = 0; ks < 4; ks++) {
            const float* sa = s[2*ks];
            const float* sb = s[2*ks+1];
            u32 ph[4], pl[4];
            ph[0] = packbf2(sa[0], sa[1]);
            ph[1] = packbf2(sa[2], sa[3]);
            ph[2] = packbf2(sb[0], sb[1]);
            ph[3] = packbf2(sb[2], sb[3]);
            #pragma unroll
            for (int r = 0; r < 4; r++) {
                const float* sv = (r < 2) ? sa : sb;
                int e = (r & 1) * 2;
                float lof = __uint_as_float((ph[r] & 0xffffu) << 16);
                float hif = __uint_as_float(ph[r] & 0xffff0000u);
                pl[r] = packbf2(sv[e] - lof, sv[e+1] - hif);
            }
            #pragma unroll
            for (int j = 0; j < 8; j++) {
                int vo = (8*j + gid)*FS + ks*16 + 2*tq;
                u32 bh[2], bl[2];
                bh[0] = *(const u32*)&sVh[vo];
                bh[1] = *(const u32*)&sVh[vo + 8];
                bl[0] = *(const u32*)&sVl[vo];
                bl[1] = *(const u32*)&sVl[vo + 8];
                mma_bf16(oa[j], ph, bh);
                mma_bf16(oa[j], ph, bl);
                mma_bf16(oa[j], pl, bh);
            }
        }
        __syncthreads();
    }

    float i0 = 1.f / l0, i1 = 1.f / l1;
    #pragma unroll
    for (int j = 0; j < 8; j++) {
        int d = h*64 + 8*j + 2*tq;
        *(float2*)(g_o + (size_t)qrow     * CD + d) =
            make_float2(oa[j][0]*i0, oa[j][1]*i0);
        *(float2*)(g_o + (size_t)(qrow+8) * CD + d) =
            make_float2(oa[j][2]*i1, oa[j][3]*i1);
    }
}

// --------------------------------- launch ----------------------------------
extern "C" void kernel_launch(void* const* d_in, const int* in_sizes, int n_in,
                              void* d_out, int out_size)
{
    (void)in_sizes; (void)n_in; (void)out_size;
    const float* x      = (const float*)d_in[0];
    const float* y      = (const float*)d_in[1];
    const float* pos    = (const float*)d_in[2];
    const float* w_qkv  = (const float*)d_in[3];
    const float* w_kv   = (const float*)d_in[4];
    const float* w_proj = (const float*)d_in[5];
    const float* b_proj = (const float*)d_in[6];
    const float* qw     = (const float*)d_in[7];
    const float* kw     = (const float*)d_in[8];
    float* out = (float*)d_out;

    float *qkv, *kv, *ob;
    cudaGetSymbolAddress((void**)&qkv, g_qkv);
    cudaGetSymbolAddress((void**)&kv,  g_kv);
    cudaGetSymbolAddress((void**)&ob,  g_o);
    __nv_bfloat16 *xh,*xl,*yh,*yl,*wqh,*wql,*wkh,*wkl,*wph,*wpl;
    cudaGetSymbolAddress((void**)&xh, g_xh);  cudaGetSymbolAddress((void**)&xl, g_xl);
    cudaGetSymbolAddress((void**)&yh, g_yh);  cudaGetSymbolAddress((void**)&yl, g_yl);
    cudaGetSymbolAddress((void**)&wqh, g_wqh); cudaGetSymbolAddress((void**)&wql, g_wql);
    cudaGetSymbolAddress((void**)&wkh, g_wkh); cudaGetSymbolAddress((void**)&wkl, g_wkl);
    cudaGetSymbolAddress((void**)&wph, g_wph); cudaGetSymbolAddress((void**)&wpl, g_wpl);

    cudaFuncSetAttribute(gemm_bf16, cudaFuncAttributeMaxDynamicSharedMemorySize, G_SMEM);
    cudaFuncSetAttribute(flash_mma, cudaFuncAttributeMaxDynamicSharedMemorySize, F_SMEM);

    split_kernel<<<(NQ*CD/4 + 255)/256, 256>>>(x, xh, xl, NQ*CD/4);
    split_kernel<<<(NQ*CD/4 + 255)/256, 256>>>(y, yh, yl, NQ*CD/4);
    split_kernel<<<(3*CD*CD/4 + 255)/256, 256>>>(w_qkv, wqh, wql, 3*CD*CD/4);
    split_kernel<<<(2*CD*CD/4 + 255)/256, 256>>>(w_kv,  wkh, wkl, 2*CD*CD/4);
    split_kernel<<<(CD*CD/4 + 255)/256, 256>>>(w_proj, wph, wpl, CD*CD/4);

    gemm_bf16<<<dim3(3072/128, 2048/128), 256, G_SMEM>>>(xh, xl, wqh, wql, qkv, nullptr, 3072);
    gemm_bf16<<<dim3(2048/128, 2048/128), 256, G_SMEM>>>(yh, yl, wkh, wkl, kv, nullptr, 2048);
    post_x<<<4096, 256>>>(pos, qw, kw);
    post_y<<<4096, 256>>>(kw);
    flash_mma<<<dim3(NQ/64, H), 128, F_SMEM>>>();
    split_kernel<<<(NQ*CD/4 + 255)/256, 256>>>(ob, xh, xl, NQ*CD/4);
    gemm_bf16<<<dim3(1024/128, 2048/128), 256, G_SMEM>>>(xh, xl, wph, wpl, out, b_proj, 1024);
}